// round 7
// baseline (speedup 1.0000x reference)
#include <cuda_runtime.h>
#include <cuda_fp16.h>
#include <cstdint>

// ExpertGather: y[b,e,k,j] = sum_i x[b, Ind[b,e,k], i] * W[e,i,j]
// B=8, T=2048, I=1024, E=16, K=256, J=1024. fp32 in/out, Ind int32 on device.
//
// Round 7: single-pass fp16 mma (validated R6: rel_err 2.9e-4) with
//  - one-time fp32->fp16 prep into __device__ scratch (same as R6)
//  - 4-stage cp.async pipeline, ONE __syncthreads per chunk
//  - fragment double-buffering across k16 steps (1 CTA/SM, regs ~160)
//  - CTA 128x128, 8 warps (2x4), warp tile 64x32, K chunks of 64

namespace {
constexpr int Bv = 8, Tv = 2048, Iv = 1024, Ev = 16, Kv = 256, Jv = 1024;
constexpr int BM = 128, BN = 128, CK = 64;
constexpr int NCHUNK = Iv / CK;          // 16
constexpr int THREADS = 256;
constexpr int STAGES = 4;

constexpr uint32_t A_STAGE = BM * CK * 2;     // 16384 B
constexpr uint32_t B_STAGE = CK * BN * 2;     // 16384 B
constexpr uint32_t OFF_A = 0;
constexpr uint32_t OFF_B = STAGES * A_STAGE;  // 65536
constexpr uint32_t SMEM_BYTES = OFF_B + STAGES * B_STAGE;  // 131072
}

__device__ __half2 g_xh[(size_t)Bv * Tv * Iv / 2];   // 32 MB scratch
__device__ __half2 g_Wh[(size_t)Ev * Iv * Jv / 2];   // 32 MB scratch

__device__ __forceinline__ uint32_t smem_u32(const void* p) {
    uint32_t a;
    asm("{ .reg .u64 t; cvta.to.shared.u64 t, %1; cvt.u32.u64 %0, t; }"
        : "=r"(a) : "l"(p));
    return a;
}

#define CP_ASYNC16(dst, src)                                              \
    asm volatile("cp.async.cg.shared.global [%0], [%1], 16;"              \
                 :: "r"(dst), "l"(src) : "memory")
#define CP_COMMIT() asm volatile("cp.async.commit_group;" ::: "memory")
#define CP_WAIT(n)  asm volatile("cp.async.wait_group %0;" :: "n"(n) : "memory")

__device__ __forceinline__ void ldsm4(uint32_t* r, uint32_t addr) {
    asm volatile(
        "ldmatrix.sync.aligned.m8n8.x4.shared.b16 {%0,%1,%2,%3}, [%4];"
        : "=r"(r[0]), "=r"(r[1]), "=r"(r[2]), "=r"(r[3]) : "r"(addr));
}
__device__ __forceinline__ void ldsm4t(uint32_t* r, uint32_t addr) {
    asm volatile(
        "ldmatrix.sync.aligned.m8n8.x4.trans.shared.b16 {%0,%1,%2,%3}, [%4];"
        : "=r"(r[0]), "=r"(r[1]), "=r"(r[2]), "=r"(r[3]) : "r"(addr));
}
__device__ __forceinline__ void mma_f16(float* c, const uint32_t* a,
                                        uint32_t b0, uint32_t b1) {
    asm volatile(
        "mma.sync.aligned.m16n8k16.row.col.f32.f16.f16.f32 "
        "{%0,%1,%2,%3}, {%4,%5,%6,%7}, {%8,%9}, {%0,%1,%2,%3};"
        : "+f"(c[0]), "+f"(c[1]), "+f"(c[2]), "+f"(c[3])
        : "r"(a[0]), "r"(a[1]), "r"(a[2]), "r"(a[3]), "r"(b0), "r"(b1));
}

// ---- prep: fp32 -> fp16 for x and W ----
__global__ __launch_bounds__(256)
void prep_half_kernel(const float* __restrict__ x, const float* __restrict__ W)
{
    const int NX4 = Bv * Tv * Iv / 4;
    const int NW4 = Ev * Iv * Jv / 4;
    const int total = NX4 + NW4;
    const int stride = gridDim.x * blockDim.x;
    for (int v = blockIdx.x * blockDim.x + threadIdx.x; v < total; v += stride) {
        float4 f;
        __half2* dst;
        if (v < NX4) {
            f = reinterpret_cast<const float4*>(x)[v];
            dst = g_xh + (size_t)v * 2;
        } else {
            f = reinterpret_cast<const float4*>(W)[v - NX4];
            dst = g_Wh + (size_t)(v - NX4) * 2;
        }
        dst[0] = __floats2half2_rn(f.x, f.y);
        dst[1] = __floats2half2_rn(f.z, f.w);
    }
}

// ---- main GEMM ----
__global__ __launch_bounds__(THREADS)
void expert_gather_mma_kernel(const int* __restrict__ Ind,
                              float* __restrict__ y)
{
    extern __shared__ char smem[];
    __shared__ int sRow[BM];
    const uint32_t sb = smem_u32(smem);
    const __half* xh = reinterpret_cast<const __half*>(g_xh);
    const __half* Wh = reinterpret_cast<const __half*>(g_Wh);

    const int tid = threadIdx.x;
    const int wid = tid >> 5;
    const int lid = tid & 31;

    const int bz = blockIdx.z;          // e*8 + b  (e slowest -> W L2 reuse)
    const int e  = bz >> 3;
    const int b  = bz & 7;
    const int mBlock = blockIdx.y;      // 0..1
    const int nBlock = blockIdx.x;      // 0..7

    const int wm = wid & 1;             // warp m (0..1) -> 64 rows
    const int wn = wid >> 1;            // warp n (0..3) -> 32 cols

    if (tid < BM) {
        int t = Ind[(b * Ev + e) * Kv + mBlock * BM + tid];  // int32!
        sRow[tid] = (b * Tv + t) * Iv;
    }
    __syncthreads();

    // ---- cp.async mappings (validated R6) ----
    const int arow = tid >> 1;
    const int ach0 = (tid & 1) * 4;
    const __half* aSrcBase = xh + sRow[arow] + ach0 * 8;
    uint32_t aDst[4];
    #pragma unroll
    for (int i = 0; i < 4; ++i) {
        int ch = ach0 + i;
        aDst[i] = (uint32_t)(arow * 128 + ((ch ^ (arow & 7)) << 4));
    }
    const int brow = tid >> 2;
    const int bch0 = (tid & 3) * 4;
    const __half* bSrcBase = Wh + ((size_t)e << 20) + (size_t)brow * Jv
                               + nBlock * BN + bch0 * 8;
    uint32_t bDst[4];
    #pragma unroll
    for (int i = 0; i < 4; ++i) {
        int ch = bch0 + i;
        bDst[i] = (uint32_t)(brow * 256 + ((ch ^ (brow & 7)) << 4));
    }

    // ---- ldmatrix lane constants (validated R6) ----
    const int aLr = (lid & 7) + ((lid >> 3) & 1) * 8;
    const int aLc = lid >> 4;
    const int lk  = ((lid >> 3) & 1) * 8 + (lid & 7);
    const int bLc = wn * 4 + (lid >> 4);

    float acc[4][4][4];
    #pragma unroll
    for (int mt = 0; mt < 4; ++mt)
        #pragma unroll
        for (int nt = 0; nt < 4; ++nt)
            #pragma unroll
            for (int q = 0; q < 4; ++q) acc[mt][nt][q] = 0.0f;

    // ---- prologue: issue chunk loads 0..STAGES-2 ----
    #pragma unroll
    for (int s = 0; s < STAGES - 1; ++s) {
        const uint32_t aB = sb + OFF_A + s * A_STAGE;
        const uint32_t bB = sb + OFF_B + s * B_STAGE;
        const int kt = s * CK;
        #pragma unroll
        for (int i = 0; i < 4; ++i) {
            CP_ASYNC16(aB + aDst[i], aSrcBase + kt + i * 8);
            CP_ASYNC16(bB + bDst[i], bSrcBase + (size_t)kt * Jv + i * 8);
        }
        CP_COMMIT();
    }

    uint32_t aF[2][16], bF[2][8];

    for (int c = 0; c < NCHUNK; ++c) {
        CP_WAIT(STAGES - 2);   // chunk c data resident
        __syncthreads();       // ...for ALL threads' cp.asyncs

        const uint32_t aB = sb + OFF_A + (c % STAGES) * A_STAGE;
        const uint32_t bB = sb + OFF_B + (c % STAGES) * B_STAGE;

        // Load fragments for ks=0 (buffer 0).
        #pragma unroll
        for (int np = 0; np < 2; ++np) {
            const int row = lk;
            const int ch  = bLc + np * 2;
            ldsm4t(bF[0] + np * 4,
                   bB + (uint32_t)(row * 256 + ((ch ^ (row & 7)) << 4)));
        }
        #pragma unroll
        for (int mt = 0; mt < 4; ++mt) {
            const int row = wm * 64 + mt * 16 + aLr;
            ldsm4(aF[0] + mt * 4,
                  aB + (uint32_t)(row * 128 + ((aLc ^ (row & 7)) << 4)));
        }

        // Issue loads for chunk c+STAGES-1 (stage buffer was consumed at c-1;
        // every warp passed compute c-1 before the sync above).
        if (c + STAGES - 1 < NCHUNK) {
            const int s = (c + STAGES - 1) % STAGES;
            const uint32_t aI = sb + OFF_A + s * A_STAGE;
            const uint32_t bI = sb + OFF_B + s * B_STAGE;
            const int kt = (c + STAGES - 1) * CK;
            #pragma unroll
            for (int i = 0; i < 4; ++i) {
                CP_ASYNC16(aI + aDst[i], aSrcBase + kt + i * 8);
                CP_ASYNC16(bI + bDst[i], bSrcBase + (size_t)kt * Jv + i * 8);
            }
        }
        CP_COMMIT();   // commit every iter to keep group<->chunk alignment

        // Fragment-pipelined compute: ldsm(ks+1) issued before mma(ks).
        #pragma unroll
        for (int ks = 0; ks < CK / 16; ++ks) {
            const int cur = ks & 1;
            if (ks + 1 < CK / 16) {
                const int nxt = cur ^ 1;
                #pragma unroll
                for (int np = 0; np < 2; ++np) {
                    const int row = (ks + 1) * 16 + lk;
                    const int ch  = bLc + np * 2;
                    ldsm4t(bF[nxt] + np * 4,
                           bB + (uint32_t)(row * 256 + ((ch ^ (row & 7)) << 4)));
                }
                #pragma unroll
                for (int mt = 0; mt < 4; ++mt) {
                    const int row = wm * 64 + mt * 16 + aLr;
                    const int ch  = (ks + 1) * 2 + aLc;
                    ldsm4(aF[nxt] + mt * 4,
                          aB + (uint32_t)(row * 128 + ((ch ^ (row & 7)) << 4)));
                }
            }
            #pragma unroll
            for (int mt = 0; mt < 4; ++mt)
                #pragma unroll
                for (int nt = 0; nt < 4; ++nt)
                    mma_f16(acc[mt][nt], aF[cur] + mt * 4,
                            bF[cur][nt * 2], bF[cur][nt * 2 + 1]);
        }
        // No trailing barrier: next iteration's top sync protects stage reuse.
    }

    // ---- epilogue (validated R5/R6 mapping) ----
    const int g  = lid >> 2;
    const int t2 = (lid & 3) * 2;
    const size_t ybase = ((size_t)(b * Ev + e) * Kv + mBlock * BM) * Jv
                         + nBlock * BN;
    #pragma unroll
    for (int mt = 0; mt < 4; ++mt) {
        const int row0 = wm * 64 + mt * 16 + g;
        #pragma unroll
        for (int nt = 0; nt < 4; ++nt) {
            const int col = wn * 32 + nt * 8 + t2;
            float2 v0 = make_float2(acc[mt][nt][0], acc[mt][nt][1]);
            float2 v1 = make_float2(acc[mt][nt][2], acc[mt][nt][3]);
            *reinterpret_cast<float2*>(y + ybase + (size_t)row0 * Jv + col) = v0;
            *reinterpret_cast<float2*>(y + ybase + (size_t)(row0 + 8) * Jv + col) = v1;
        }
    }
}

extern "C" void kernel_launch(void* const* d_in, const int* in_sizes, int n_in,
                              void* d_out, int out_size)
{
    const float* x   = (const float*)d_in[0];  // [8, 2048, 1024] f32
    const float* W   = (const float*)d_in[1];  // [16, 1024, 1024] f32
    const int*   Ind = (const int*)d_in[2];    // [8, 16, 256] i32 (JAX x64 off)
    float*       y   = (float*)d_out;          // [8, 16, 256, 1024] f32
    (void)in_sizes; (void)n_in; (void)out_size;

    static int attr_set = 0;
    if (!attr_set) {
        cudaFuncSetAttribute(expert_gather_mma_kernel,
                             cudaFuncAttributeMaxDynamicSharedMemorySize,
                             SMEM_BYTES);
        attr_set = 1;
    }

    prep_half_kernel<<<4096, 256>>>(x, W);

    dim3 grid(Jv / BN, Kv / BM, Bv * Ev);  // (8, 2, 128)
    expert_gather_mma_kernel<<<grid, THREADS, SMEM_BYTES>>>(Ind, y);
}